// round 3
// baseline (speedup 1.0000x reference)
#include <cuda_runtime.h>
#include <math.h>

// Problem constants
constexpr int NB  = 8;
constexpr int NT  = 2048;
constexpr int ND  = 1024;
constexpr int NP  = 512;
constexpr int NS  = 256;
constexpr int NH  = 256;
constexpr int NBT = NB * NT;      // 16384

constexpr float TAUF = 1e-5f;     // at-risk flag window (fp32 pass error ~1e-6)

// ---------------- device scratch (static allocations only) ----------------
__device__ float g_h[NBT * NH];          // tokens@w1 (pre-relu)
__device__ float g_q[NBT * NS];          // tokens@wq
__device__ float g_scores[NBT];
__device__ int   g_order[NBT];           // per-batch sorted token indices
__device__ float g_sscores[NBT];         // per-batch sorted scores
__device__ float g_st[NB * NP * ND];     // top-512 sorted tokens
__device__ float g_sum[NB * NP * NS];    // summaries
__device__ float g_pool[NB * NP * NS];   // updated pool
__device__ float g_pri[NB * NP];
__device__ int   g_counts[NB];
__device__ float g_k[NB * NP * NS];      // pool@wk
__device__ float g_kT[NB * NS * NP];     // transposed k
__device__ float g_v[NB * NP * ND];      // pool@wv
__device__ float g_attn[NB * NT * NP];   // attention weights
__device__ int           g_flagcnt;
__device__ int           g_flaglist[NBT];
__device__ unsigned char g_flag[NBT];

// ---------------- generic batched SGEMM: C = A(MxK) @ B(KxN), row-major ----
__global__ void sgemm_kernel(const float* __restrict__ A, const float* __restrict__ Bm,
                             float* __restrict__ C, int M, int N, int K,
                             long long sA, long long sB, long long sC) {
    A  += (long long)blockIdx.z * sA;
    Bm += (long long)blockIdx.z * sB;
    C  += (long long)blockIdx.z * sC;
    __shared__ float As[16][64];   // k-major
    __shared__ float Bs[16][64];
    const int tid = threadIdx.x;
    const int tx = tid & 15, ty = tid >> 4;
    const int row0 = blockIdx.y * 64, col0 = blockIdx.x * 64;
    const int ar = tid >> 2, ac = (tid & 3) << 2;
    const int br = tid >> 4, bc = (tid & 15) << 2;
    const float* Ap = A + (long long)(row0 + ar) * K + ac;
    const float* Bp = Bm + (long long)br * N + col0 + bc;
    float acc[4][4] = {};
    for (int k0 = 0; k0 < K; k0 += 16) {
        float4 av = *(const float4*)Ap;
        float4 bv = *(const float4*)Bp;
        As[ac + 0][ar] = av.x;
        As[ac + 1][ar] = av.y;
        As[ac + 2][ar] = av.z;
        As[ac + 3][ar] = av.w;
        *(float4*)&Bs[br][bc] = bv;
        __syncthreads();
#pragma unroll
        for (int kk = 0; kk < 16; kk++) {
            float4 a4 = *(const float4*)&As[kk][ty << 2];
            float4 b4 = *(const float4*)&Bs[kk][tx << 2];
            acc[0][0] = fmaf(a4.x, b4.x, acc[0][0]);
            acc[0][1] = fmaf(a4.x, b4.y, acc[0][1]);
            acc[0][2] = fmaf(a4.x, b4.z, acc[0][2]);
            acc[0][3] = fmaf(a4.x, b4.w, acc[0][3]);
            acc[1][0] = fmaf(a4.y, b4.x, acc[1][0]);
            acc[1][1] = fmaf(a4.y, b4.y, acc[1][1]);
            acc[1][2] = fmaf(a4.y, b4.z, acc[1][2]);
            acc[1][3] = fmaf(a4.y, b4.w, acc[1][3]);
            acc[2][0] = fmaf(a4.z, b4.x, acc[2][0]);
            acc[2][1] = fmaf(a4.z, b4.y, acc[2][1]);
            acc[2][2] = fmaf(a4.z, b4.z, acc[2][2]);
            acc[2][3] = fmaf(a4.z, b4.w, acc[2][3]);
            acc[3][0] = fmaf(a4.w, b4.x, acc[3][0]);
            acc[3][1] = fmaf(a4.w, b4.y, acc[3][1]);
            acc[3][2] = fmaf(a4.w, b4.z, acc[3][2]);
            acc[3][3] = fmaf(a4.w, b4.w, acc[3][3]);
        }
        __syncthreads();
        Ap += 16;
        Bp += (long long)16 * N;
    }
#pragma unroll
    for (int i = 0; i < 4; i++) {
        float4 o = make_float4(acc[i][0], acc[i][1], acc[i][2], acc[i][3]);
        *(float4*)&C[(long long)(row0 + (ty << 2) + i) * N + col0 + (tx << 2)] = o;
    }
}

// ---------------- scores: sigmoid(relu(h) . w2), one warp per row ----------
__global__ void score_kernel(const float* __restrict__ w2) {
    int gw = (blockIdx.x * blockDim.x + threadIdx.x) >> 5;
    int lane = threadIdx.x & 31;
    if (gw >= NBT) return;
    const float* hr = g_h + (long long)gw * NH;
    float s = 0.f;
#pragma unroll
    for (int j = 0; j < NH / 32; j++) {
        int c = lane + (j << 5);
        float v = hr[c];
        v = fmaxf(v, 0.f);
        s = fmaf(v, w2[c], s);
    }
#pragma unroll
    for (int o = 16; o; o >>= 1) s += __shfl_xor_sync(0xffffffffu, s, o);
    if (lane == 0) g_scores[gw] = 1.0f / (1.0f + expf(-s));
}

// ---------------- per-batch bitonic sort, descending score / ascending idx --
__global__ void sort_kernel() {
    __shared__ float sk[NT];
    __shared__ int   si[NT];
    int b = blockIdx.x, t = threadIdx.x;   // 1024 threads
    sk[t]        = g_scores[b * NT + t];        si[t]        = t;
    sk[t + 1024] = g_scores[b * NT + t + 1024]; si[t + 1024] = t + 1024;
    __syncthreads();
    for (int kk = 2; kk <= NT; kk <<= 1) {
        for (int j = kk >> 1; j > 0; j >>= 1) {
            for (int i = t; i < NT; i += 1024) {
                int ixj = i ^ j;
                if (ixj > i) {
                    bool ord = ((i & kk) == 0);
                    float s1 = sk[i], s2 = sk[ixj];
                    int   i1 = si[i], i2 = si[ixj];
                    bool pre = (s2 > s1) || (s2 == s1 && i2 < i1);
                    if (pre == ord) { sk[i] = s2; sk[ixj] = s1; si[i] = i2; si[ixj] = i1; }
                }
            }
            __syncthreads();
        }
    }
    g_order[b * NT + t]          = si[t];
    g_order[b * NT + t + 1024]   = si[t + 1024];
    g_sscores[b * NT + t]        = sk[t];
    g_sscores[b * NT + t + 1024] = sk[t + 1024];
}

// ---------------- at-risk flagging ----------------
__global__ void reset_flags_kernel() {
    int i = blockIdx.x * blockDim.x + threadIdx.x;
    if (i < NBT) g_flag[i] = 0;
    if (i == 0) g_flagcnt = 0;
}

// A: adjacent sorted near-ties; B: near TAU1 threshold
__global__ void flag_ab_kernel() {
    int i = blockIdx.x * blockDim.x + threadIdx.x;   // global sorted position
    if (i >= NBT) return;
    int b = i >> 11, p = i & (NT - 1);
    float s = g_sscores[i];
    if (fabsf(s - 0.5f) < TAUF) g_flag[b * NT + g_order[i]] = 1;
    if (p + 1 < NT) {
        float s2 = g_sscores[i + 1];
        if (fabsf(s - s2) < TAUF) {
            g_flag[b * NT + g_order[i]] = 1;
            g_flag[b * NT + g_order[i + 1]] = 1;
        }
    }
}

// C: score within TAUF of any input priority of its batch
__global__ void flag_c_kernel(const float* __restrict__ pri_in) {
    __shared__ float pr[NP];
    int b = blockIdx.y;
    for (int i = threadIdx.x; i < NP; i += blockDim.x) pr[i] = pri_in[b * NP + i];
    __syncthreads();
    int t = blockIdx.x * blockDim.x + threadIdx.x;   // token within batch
    if (t >= NT) return;
    float s = g_scores[b * NT + t];
    bool hit = false;
#pragma unroll 8
    for (int i = 0; i < NP; i++) hit |= (fabsf(s - pr[i]) < TAUF);
    if (hit) g_flag[b * NT + t] = 1;
}

__global__ void compact_kernel() {
    int i = blockIdx.x * blockDim.x + threadIdx.x;
    if (i < NBT && g_flag[i]) {
        int pos = atomicAdd(&g_flagcnt, 1);
        g_flaglist[pos] = i;
    }
}

// exact fp64 recompute of flagged tokens' scores (staged rounding as reference)
__global__ void recompute_kernel(const float* __restrict__ tokens,
                                 const float* __restrict__ w1,
                                 const float* __restrict__ w2) {
    __shared__ double red[256];
    int j = threadIdx.x;   // 256 threads = H columns
    int n = g_flagcnt;
    if (blockIdx.x >= n) return;
    for (int li = blockIdx.x; li < n; li += gridDim.x) {
        int g = g_flaglist[li];
        const float* x = tokens + (long long)g * ND;
        double acc = 0.0;
        const float* wcol = w1 + j;
        for (int d = 0; d < ND; d++)
            acc += (double)x[d] * (double)wcol[(long long)d * NH];
        float hf = fmaxf((float)acc, 0.0f);      // round to fp32, relu
        red[j] = (double)hf * (double)w2[j];
        __syncthreads();
        for (int s = 128; s; s >>= 1) {
            if (j < s) red[j] += red[j + s];
            __syncthreads();
        }
        if (j == 0) {
            double z = red[0];
            g_scores[g] = (float)(1.0 / (1.0 + exp(-z)));
        }
        __syncthreads();
    }
}

// ---------------- gather top-512 sorted tokens ----------------
__global__ void gather_kernel(const float* __restrict__ tokens) {
    int b = blockIdx.y, slot = blockIdx.x;
    int src = g_order[b * NT + slot];
    const float4* s4 = (const float4*)(tokens + ((long long)b * NT + src) * ND);
    float4* d4 = (float4*)(g_st + ((long long)b * NP + slot) * ND);
    d4[threadIdx.x] = s4[threadIdx.x];
}

// ---------------- sequential pool update (exact reference semantics) -------
__global__ void update_kernel(const float* __restrict__ pool_in,
                              const float* __restrict__ pri_in,
                              const int* __restrict__ counts_in) {
    int b = blockIdx.x, t = threadIdx.x;   // 256 threads
    __shared__ float pri[NP];
    __shared__ int   sh_cnt;
    __shared__ float sh_minp;
    __shared__ int   sh_mini;
    const float4* pin  = (const float4*)(pool_in + (long long)b * NP * NS);
    float4*       pout = (float4*)(g_pool + (long long)b * NP * NS);
    for (int i = t; i < NP * NS / 4; i += 256) pout[i] = pin[i];
    pri[t]       = pri_in[b * NP + t];
    pri[t + 256] = pri_in[b * NP + t + 256];
    if (t == 0) sh_cnt = counts_in[b];
    __syncthreads();

    float*       poolb = g_pool + (long long)b * NP * NS;
    const float* summb = g_sum + (long long)b * NP * NS;
    const float* ss    = g_sscores + b * NT;

    for (int slot = 0; slot < NP; slot++) {
        float sc = ss[slot];
        bool has = sc > 0.5f;
        int cnt = sh_cnt;
        if (has && cnt < NP) {                // insert phase
            poolb[cnt * NS + t] = summb[slot * NS + t];
            __syncthreads();
            if (t == 0) { pri[cnt] = sc; sh_cnt = cnt + 1; }
        }
        __syncthreads();
        if (has && sh_cnt >= NP) {            // replace-min (post-insert count)
            if (t < 32) {
                float best = 1e30f; int bidx = 0;
#pragma unroll
                for (int jj = 0; jj < NP / 32; jj++) {
                    int idx = t + (jj << 5);
                    float v = pri[idx];
                    if (v < best) { best = v; bidx = idx; }
                }
#pragma unroll
                for (int o = 16; o; o >>= 1) {
                    float ov = __shfl_xor_sync(0xffffffffu, best, o);
                    int   oi = __shfl_xor_sync(0xffffffffu, bidx, o);
                    if (ov < best || (ov == best && oi < bidx)) { best = ov; bidx = oi; }
                }
                if (t == 0) { sh_minp = best; sh_mini = bidx; }
            }
            __syncthreads();
            if (sc > sh_minp) {
                poolb[sh_mini * NS + t] = summb[slot * NS + t];
                if (t == 0) pri[sh_mini] = sc;
            }
            __syncthreads();
        }
    }
    __syncthreads();
    g_pri[b * NP + t]       = pri[t];
    g_pri[b * NP + t + 256] = pri[t + 256];
    if (t == 0) g_counts[b] = sh_cnt;
}

// ---------------- transpose k[b,P,S] -> kT[b,S,P] ----------------
__global__ void transpose_kernel() {
    __shared__ float tile[32][33];
    int b = blockIdx.z;
    int p0 = blockIdx.x * 32, s0 = blockIdx.y * 32;
    const float* src = g_k + (long long)b * NP * NS;
    float* dst = g_kT + (long long)b * NS * NP;
    int x = threadIdx.x, y = threadIdx.y;
#pragma unroll
    for (int i = 0; i < 32; i += 8)
        tile[y + i][x] = src[(p0 + y + i) * NS + s0 + x];
    __syncthreads();
#pragma unroll
    for (int i = 0; i < 32; i += 8)
        dst[(s0 + y + i) * NP + p0 + x] = tile[x][y + i];
}

// ---------------- masked softmax over attn rows (warp per row) -------------
__global__ void softmax_kernel() {
    int gw = (blockIdx.x * blockDim.x + threadIdx.x) >> 5;
    int lane = threadIdx.x & 31;
    if (gw >= NBT) return;
    int b = gw >> 11;
    int cnt = g_counts[b];
    float* row = g_attn + (long long)gw * NP;
    float vals[NP / 32];
    float m = -1e30f;
#pragma unroll
    for (int j = 0; j < NP / 32; j++) {
        int p = lane + (j << 5);
        float v = row[p] * 0.0625f;   // 1/sqrt(256)
        vals[j] = v;
        if (p < cnt) m = fmaxf(m, v);
    }
#pragma unroll
    for (int o = 16; o; o >>= 1) m = fmaxf(m, __shfl_xor_sync(0xffffffffu, m, o));
    float s = 0.f;
#pragma unroll
    for (int j = 0; j < NP / 32; j++) {
        int p = lane + (j << 5);
        float e = (p < cnt) ? expf(vals[j] - m) : 0.f;
        vals[j] = e;
        s += e;
    }
#pragma unroll
    for (int o = 16; o; o >>= 1) s += __shfl_xor_sync(0xffffffffu, s, o);
    float inv = (cnt > 0) ? 1.f / s : 0.f;
#pragma unroll
    for (int j = 0; j < NP / 32; j++) row[lane + (j << 5)] = vals[j] * inv;
}

// ---------------- export pool / priorities / counts into d_out -------------
__global__ void export_kernel(float* __restrict__ dst) {
    int i = blockIdx.x * blockDim.x + threadIdx.x;
    constexpr int PS = NB * NP * NS;
    if (i < PS) dst[i] = g_pool[i];
    else if (i < PS + NB * NP) dst[i] = g_pri[i - PS];
    else if (i < PS + NB * NP + NB) dst[i] = (float)g_counts[i - PS - NB * NP];
}

// ---------------- launch ----------------
extern "C" void kernel_launch(void* const* d_in, const int* in_sizes, int n_in,
                              void* d_out, int out_size) {
    const float* tokens = (const float*)d_in[0];
    const float* pool   = (const float*)d_in[1];
    const float* pri    = (const float*)d_in[2];
    const int*   counts = (const int*)d_in[3];
    const float* w1     = (const float*)d_in[4];
    const float* w2     = (const float*)d_in[5];
    const float* w_sum  = (const float*)d_in[6];
    const float* wq     = (const float*)d_in[7];
    const float* wk     = (const float*)d_in[8];
    const float* wv     = (const float*)d_in[9];
    float* out = (float*)d_out;
    (void)in_sizes; (void)n_in;

    float *ph, *pq, *pst, *psum, *ppool, *pk, *pkT, *pv, *pattn;
    cudaGetSymbolAddress((void**)&ph,    g_h);
    cudaGetSymbolAddress((void**)&pq,    g_q);
    cudaGetSymbolAddress((void**)&pst,   g_st);
    cudaGetSymbolAddress((void**)&psum,  g_sum);
    cudaGetSymbolAddress((void**)&ppool, g_pool);
    cudaGetSymbolAddress((void**)&pk,    g_k);
    cudaGetSymbolAddress((void**)&pkT,   g_kT);
    cudaGetSymbolAddress((void**)&pv,    g_v);
    cudaGetSymbolAddress((void**)&pattn, g_attn);

    // 1. h = tokens @ w1
    sgemm_kernel<<<dim3(NH / 64, NBT / 64, 1), 256>>>(tokens, w1, ph, NBT, NH, ND, 0, 0, 0);
    // 2. q = tokens @ wq
    sgemm_kernel<<<dim3(NS / 64, NBT / 64, 1), 256>>>(tokens, wq, pq, NBT, NS, ND, 0, 0, 0);
    // 3. scores (fp32 fast pass)
    score_kernel<<<NBT / 8, 256>>>(w2);
    // 4. provisional sort
    sort_kernel<<<NB, 1024>>>();
    // 5. flag at-risk tokens and recompute them exactly (fp64)
    reset_flags_kernel<<<NBT / 256, 256>>>();
    flag_ab_kernel<<<NBT / 256, 256>>>();
    flag_c_kernel<<<dim3(NT / 256, NB), 256>>>(pri);
    compact_kernel<<<NBT / 256, 256>>>();
    recompute_kernel<<<512, 256>>>(tokens, w1, w2);
    // 6. final sort with corrected scores
    sort_kernel<<<NB, 1024>>>();
    // 7. gather top-512 tokens
    gather_kernel<<<dim3(NP, NB), 256>>>(tokens);
    // 8. summaries = sorted_tokens @ w_sum
    sgemm_kernel<<<dim3(NS / 64, NB * NP / 64, 1), 256>>>(pst, w_sum, psum, NB * NP, NS, ND, 0, 0, 0);
    // 9. sequential pool update
    update_kernel<<<NB, 256>>>(pool, pri, counts);
    // 10. k = pool @ wk
    sgemm_kernel<<<dim3(NS / 64, NB * NP / 64, 1), 256>>>(ppool, wk, pk, NB * NP, NS, NS, 0, 0, 0);
    // 11. transpose k -> kT
    transpose_kernel<<<dim3(NP / 32, NS / 32, NB), dim3(32, 8)>>>();
    // 12. v = pool @ wv
    sgemm_kernel<<<dim3(ND / 64, NB * NP / 64, 1), 256>>>(ppool, wv, pv, NB * NP, ND, NS, 0, 0, 0);
    // 13. attn = q @ kT  (batched)
    sgemm_kernel<<<dim3(NP / 64, NT / 64, NB), 256>>>(pq, pkT, pattn, NT, NP, NS,
        (long long)NT * NS, (long long)NS * NP, (long long)NT * NP);
    // 14. masked softmax
    softmax_kernel<<<NBT / 8, 256>>>();
    // 15. retrieved = attn @ v  (batched) -> d_out
    sgemm_kernel<<<dim3(ND / 64, NT / 64, NB), 256>>>(pattn, pv, out, NT, ND, NP,
        (long long)NT * NP, (long long)NP * ND, (long long)NT * ND);
    // 16. export pool / priorities / counts
    constexpr int RET = NBT * ND;
    constexpr int REST = NB * NP * NS + NB * NP + NB;
    if (out_size >= RET + REST)
        export_kernel<<<(REST + 255) / 256, 256>>>(out + (long long)RET);
}

// round 4
// speedup vs baseline: 1.0516x; 1.0516x over previous
#include <cuda_runtime.h>
#include <math.h>

// Problem constants
constexpr int NB  = 8;
constexpr int NT  = 2048;
constexpr int ND  = 1024;
constexpr int NP  = 512;
constexpr int NS  = 256;
constexpr int NH  = 256;
constexpr int NBT = NB * NT;      // 16384

constexpr float TAUF = 1e-5f;     // at-risk flag window (fp32 pass error ~1e-6)

// ---------------- device scratch (static allocations only) ----------------
__device__ float g_h[NBT * NH];          // tokens@w1 (pre-relu)
__device__ float g_q[NBT * NS];          // tokens@wq
__device__ float g_scores[NBT];
__device__ int   g_order[NBT];           // per-batch sorted token indices
__device__ float g_sscores[NBT];         // per-batch sorted scores
__device__ float g_st[NB * NP * ND];     // top-512 sorted tokens
__device__ float g_sum[NB * NP * NS];    // summaries
__device__ float g_pool[NB * NP * NS];   // updated pool
__device__ float g_pri[NB * NP];
__device__ int   g_counts[NB];
__device__ float g_k[NB * NP * NS];      // pool@wk
__device__ float g_kT[NB * NS * NP];     // transposed k
__device__ float g_v[NB * NP * ND];      // pool@wv
__device__ float g_attn[NB * NT * NP];   // attention weights
__device__ int           g_flagcnt;
__device__ int           g_flaglist[NBT];
__device__ unsigned char g_flag[NBT];

// ------- 128x128x8 double-buffered SGEMM, 8x8 microtile, 256 threads -------
// C = A(MxK) @ B(KxN), row-major; M%128==0, N%128==0, K%8==0 (all shapes here).
__global__ __launch_bounds__(256, 2)
void sgemm128_kernel(const float* __restrict__ A, const float* __restrict__ Bm,
                     float* __restrict__ C, int M, int N, int K,
                     long long sA, long long sB, long long sC) {
    A  += (long long)blockIdx.z * sA;
    Bm += (long long)blockIdx.z * sB;
    C  += (long long)blockIdx.z * sC;
    __shared__ float As[2][8][128];    // k-major (transposed on store)
    __shared__ float Bs[2][8][128];

    const int tid  = threadIdx.x;
    const int row0 = blockIdx.y * 128, col0 = blockIdx.x * 128;
    // A tile load: 128 rows x 8 cols; each thread one float4
    const int ar = tid >> 1;              // 0..127
    const int ac = (tid & 1) << 2;        // 0 or 4
    // B tile load: 8 rows x 128 cols; each thread one float4
    const int br = tid >> 5;              // 0..7
    const int bc = (tid & 31) << 2;       // 0..124
    const float* Ap = A + (long long)(row0 + ar) * K + ac;
    const float* Bp = Bm + (long long)br * N + col0 + bc;
    // microtile coords: 16x16 thread grid, each 8x8
    const int tx = (tid & 15) << 3;       // col offset
    const int ty = (tid >> 4) << 3;       // row offset

    float acc[8][8] = {};
    float4 av = *(const float4*)Ap;
    float4 bv = *(const float4*)Bp;
    int buf = 0;
    As[0][ac + 0][ar] = av.x;
    As[0][ac + 1][ar] = av.y;
    As[0][ac + 2][ar] = av.z;
    As[0][ac + 3][ar] = av.w;
    *(float4*)&Bs[0][br][bc] = bv;
    __syncthreads();

    for (int k0 = 8; k0 <= K; k0 += 8) {
        if (k0 < K) {                       // prefetch next tile into regs
            av = *(const float4*)(Ap + k0);
            bv = *(const float4*)(Bp + (long long)k0 * N);
        }
#pragma unroll
        for (int kk = 0; kk < 8; kk++) {
            float a[8], b[8];
            *(float4*)&a[0] = *(const float4*)&As[buf][kk][ty];
            *(float4*)&a[4] = *(const float4*)&As[buf][kk][ty + 4];
            *(float4*)&b[0] = *(const float4*)&Bs[buf][kk][tx];
            *(float4*)&b[4] = *(const float4*)&Bs[buf][kk][tx + 4];
#pragma unroll
            for (int i = 0; i < 8; i++)
#pragma unroll
                for (int j = 0; j < 8; j++)
                    acc[i][j] = fmaf(a[i], b[j], acc[i][j]);
        }
        if (k0 < K) {
            buf ^= 1;
            As[buf][ac + 0][ar] = av.x;
            As[buf][ac + 1][ar] = av.y;
            As[buf][ac + 2][ar] = av.z;
            As[buf][ac + 3][ar] = av.w;
            *(float4*)&Bs[buf][br][bc] = bv;
            __syncthreads();
        }
    }
#pragma unroll
    for (int i = 0; i < 8; i++) {
        float* crow = C + (long long)(row0 + ty + i) * N + col0 + tx;
        *(float4*)crow       = make_float4(acc[i][0], acc[i][1], acc[i][2], acc[i][3]);
        *(float4*)(crow + 4) = make_float4(acc[i][4], acc[i][5], acc[i][6], acc[i][7]);
    }
}

// ---------------- scores: sigmoid(relu(h) . w2), one warp per row ----------
__global__ void score_kernel(const float* __restrict__ w2) {
    int gw = (blockIdx.x * blockDim.x + threadIdx.x) >> 5;
    int lane = threadIdx.x & 31;
    if (gw >= NBT) return;
    const float* hr = g_h + (long long)gw * NH;
    float s = 0.f;
#pragma unroll
    for (int j = 0; j < NH / 32; j++) {
        int c = lane + (j << 5);
        float v = hr[c];
        v = fmaxf(v, 0.f);
        s = fmaf(v, w2[c], s);
    }
#pragma unroll
    for (int o = 16; o; o >>= 1) s += __shfl_xor_sync(0xffffffffu, s, o);
    if (lane == 0) g_scores[gw] = 1.0f / (1.0f + expf(-s));
}

// ---------------- per-batch bitonic sort, descending score / ascending idx --
__global__ void sort_kernel() {
    __shared__ float sk[NT];
    __shared__ int   si[NT];
    int b = blockIdx.x, t = threadIdx.x;   // 1024 threads
    sk[t]        = g_scores[b * NT + t];        si[t]        = t;
    sk[t + 1024] = g_scores[b * NT + t + 1024]; si[t + 1024] = t + 1024;
    __syncthreads();
    for (int kk = 2; kk <= NT; kk <<= 1) {
        for (int j = kk >> 1; j > 0; j >>= 1) {
            for (int i = t; i < NT; i += 1024) {
                int ixj = i ^ j;
                if (ixj > i) {
                    bool ord = ((i & kk) == 0);
                    float s1 = sk[i], s2 = sk[ixj];
                    int   i1 = si[i], i2 = si[ixj];
                    bool pre = (s2 > s1) || (s2 == s1 && i2 < i1);
                    if (pre == ord) { sk[i] = s2; sk[ixj] = s1; si[i] = i2; si[ixj] = i1; }
                }
            }
            __syncthreads();
        }
    }
    g_order[b * NT + t]          = si[t];
    g_order[b * NT + t + 1024]   = si[t + 1024];
    g_sscores[b * NT + t]        = sk[t];
    g_sscores[b * NT + t + 1024] = sk[t + 1024];
}

// ---------------- at-risk flagging ----------------
__global__ void reset_flags_kernel() {
    int i = blockIdx.x * blockDim.x + threadIdx.x;
    if (i < NBT) g_flag[i] = 0;
    if (i == 0) g_flagcnt = 0;
}

// A: adjacent sorted near-ties; B: near TAU1 threshold
__global__ void flag_ab_kernel() {
    int i = blockIdx.x * blockDim.x + threadIdx.x;   // global sorted position
    if (i >= NBT) return;
    int b = i >> 11, p = i & (NT - 1);
    float s = g_sscores[i];
    if (fabsf(s - 0.5f) < TAUF) g_flag[b * NT + g_order[i]] = 1;
    if (p + 1 < NT) {
        float s2 = g_sscores[i + 1];
        if (fabsf(s - s2) < TAUF) {
            g_flag[b * NT + g_order[i]] = 1;
            g_flag[b * NT + g_order[i + 1]] = 1;
        }
    }
}

// C: score within TAUF of any input priority of its batch
__global__ void flag_c_kernel(const float* __restrict__ pri_in) {
    __shared__ float pr[NP];
    int b = blockIdx.y;
    for (int i = threadIdx.x; i < NP; i += blockDim.x) pr[i] = pri_in[b * NP + i];
    __syncthreads();
    int t = blockIdx.x * blockDim.x + threadIdx.x;   // token within batch
    if (t >= NT) return;
    float s = g_scores[b * NT + t];
    bool hit = false;
#pragma unroll 8
    for (int i = 0; i < NP; i++) hit |= (fabsf(s - pr[i]) < TAUF);
    if (hit) g_flag[b * NT + t] = 1;
}

__global__ void compact_kernel() {
    int i = blockIdx.x * blockDim.x + threadIdx.x;
    if (i < NBT && g_flag[i]) {
        int pos = atomicAdd(&g_flagcnt, 1);
        g_flaglist[pos] = i;
    }
}

// exact fp64 recompute of flagged tokens' scores (staged rounding as reference)
__global__ void recompute_kernel(const float* __restrict__ tokens,
                                 const float* __restrict__ w1,
                                 const float* __restrict__ w2) {
    __shared__ double red[256];
    int j = threadIdx.x;   // 256 threads = H columns
    int n = g_flagcnt;
    if (blockIdx.x >= n) return;
    for (int li = blockIdx.x; li < n; li += gridDim.x) {
        int g = g_flaglist[li];
        const float* x = tokens + (long long)g * ND;
        double acc = 0.0;
        const float* wcol = w1 + j;
        for (int d = 0; d < ND; d++)
            acc += (double)x[d] * (double)wcol[(long long)d * NH];
        float hf = fmaxf((float)acc, 0.0f);      // round to fp32, relu
        red[j] = (double)hf * (double)w2[j];
        __syncthreads();
        for (int s = 128; s; s >>= 1) {
            if (j < s) red[j] += red[j + s];
            __syncthreads();
        }
        if (j == 0) {
            double z = red[0];
            g_scores[g] = (float)(1.0 / (1.0 + exp(-z)));
        }
        __syncthreads();
    }
}

// ---------------- gather top-512 sorted tokens ----------------
__global__ void gather_kernel(const float* __restrict__ tokens) {
    int b = blockIdx.y, slot = blockIdx.x;
    int src = g_order[b * NT + slot];
    const float4* s4 = (const float4*)(tokens + ((long long)b * NT + src) * ND);
    float4* d4 = (float4*)(g_st + ((long long)b * NP + slot) * ND);
    d4[threadIdx.x] = s4[threadIdx.x];
}

// ---------------- sequential pool update (exact reference semantics) -------
__global__ void update_kernel(const float* __restrict__ pool_in,
                              const float* __restrict__ pri_in,
                              const int* __restrict__ counts_in) {
    int b = blockIdx.x, t = threadIdx.x;   // 256 threads
    __shared__ float pri[NP];
    __shared__ int   sh_cnt;
    __shared__ float sh_minp;
    __shared__ int   sh_mini;
    const float4* pin  = (const float4*)(pool_in + (long long)b * NP * NS);
    float4*       pout = (float4*)(g_pool + (long long)b * NP * NS);
    for (int i = t; i < NP * NS / 4; i += 256) pout[i] = pin[i];
    pri[t]       = pri_in[b * NP + t];
    pri[t + 256] = pri_in[b * NP + t + 256];
    if (t == 0) sh_cnt = counts_in[b];
    __syncthreads();

    float*       poolb = g_pool + (long long)b * NP * NS;
    const float* summb = g_sum + (long long)b * NP * NS;
    const float* ss    = g_sscores + b * NT;

    for (int slot = 0; slot < NP; slot++) {
        float sc = ss[slot];
        bool has = sc > 0.5f;
        int cnt = sh_cnt;
        if (has && cnt < NP) {                // insert phase
            poolb[cnt * NS + t] = summb[slot * NS + t];
            __syncthreads();
            if (t == 0) { pri[cnt] = sc; sh_cnt = cnt + 1; }
        }
        __syncthreads();
        if (has && sh_cnt >= NP) {            // replace-min (post-insert count)
            if (t < 32) {
                float best = 1e30f; int bidx = 0;
#pragma unroll
                for (int jj = 0; jj < NP / 32; jj++) {
                    int idx = t + (jj << 5);
                    float v = pri[idx];
                    if (v < best) { best = v; bidx = idx; }
                }
#pragma unroll
                for (int o = 16; o; o >>= 1) {
                    float ov = __shfl_xor_sync(0xffffffffu, best, o);
                    int   oi = __shfl_xor_sync(0xffffffffu, bidx, o);
                    if (ov < best || (ov == best && oi < bidx)) { best = ov; bidx = oi; }
                }
                if (t == 0) { sh_minp = best; sh_mini = bidx; }
            }
            __syncthreads();
            if (sc > sh_minp) {
                poolb[sh_mini * NS + t] = summb[slot * NS + t];
                if (t == 0) pri[sh_mini] = sc;
            }
            __syncthreads();
        }
    }
    __syncthreads();
    g_pri[b * NP + t]       = pri[t];
    g_pri[b * NP + t + 256] = pri[t + 256];
    if (t == 0) g_counts[b] = sh_cnt;
}

// ---------------- transpose k[b,P,S] -> kT[b,S,P] ----------------
__global__ void transpose_kernel() {
    __shared__ float tile[32][33];
    int b = blockIdx.z;
    int p0 = blockIdx.x * 32, s0 = blockIdx.y * 32;
    const float* src = g_k + (long long)b * NP * NS;
    float* dst = g_kT + (long long)b * NS * NP;
    int x = threadIdx.x, y = threadIdx.y;
#pragma unroll
    for (int i = 0; i < 32; i += 8)
        tile[y + i][x] = src[(p0 + y + i) * NS + s0 + x];
    __syncthreads();
#pragma unroll
    for (int i = 0; i < 32; i += 8)
        dst[(s0 + y + i) * NP + p0 + x] = tile[x][y + i];
}

// ---------------- masked softmax over attn rows (warp per row) -------------
__global__ void softmax_kernel() {
    int gw = (blockIdx.x * blockDim.x + threadIdx.x) >> 5;
    int lane = threadIdx.x & 31;
    if (gw >= NBT) return;
    int b = gw >> 11;
    int cnt = g_counts[b];
    float* row = g_attn + (long long)gw * NP;
    float vals[NP / 32];
    float m = -1e30f;
#pragma unroll
    for (int j = 0; j < NP / 32; j++) {
        int p = lane + (j << 5);
        float v = row[p] * 0.0625f;   // 1/sqrt(256)
        vals[j] = v;
        if (p < cnt) m = fmaxf(m, v);
    }
#pragma unroll
    for (int o = 16; o; o >>= 1) m = fmaxf(m, __shfl_xor_sync(0xffffffffu, m, o));
    float s = 0.f;
#pragma unroll
    for (int j = 0; j < NP / 32; j++) {
        int p = lane + (j << 5);
        float e = (p < cnt) ? expf(vals[j] - m) : 0.f;
        vals[j] = e;
        s += e;
    }
#pragma unroll
    for (int o = 16; o; o >>= 1) s += __shfl_xor_sync(0xffffffffu, s, o);
    float inv = (cnt > 0) ? 1.f / s : 0.f;
#pragma unroll
    for (int j = 0; j < NP / 32; j++) row[lane + (j << 5)] = vals[j] * inv;
}

// ---------------- export pool / priorities / counts into d_out -------------
__global__ void export_kernel(float* __restrict__ dst) {
    int i = blockIdx.x * blockDim.x + threadIdx.x;
    constexpr int PS = NB * NP * NS;
    if (i < PS) dst[i] = g_pool[i];
    else if (i < PS + NB * NP) dst[i] = g_pri[i - PS];
    else if (i < PS + NB * NP + NB) dst[i] = (float)g_counts[i - PS - NB * NP];
}

// ---------------- launch ----------------
extern "C" void kernel_launch(void* const* d_in, const int* in_sizes, int n_in,
                              void* d_out, int out_size) {
    const float* tokens = (const float*)d_in[0];
    const float* pool   = (const float*)d_in[1];
    const float* pri    = (const float*)d_in[2];
    const int*   counts = (const int*)d_in[3];
    const float* w1     = (const float*)d_in[4];
    const float* w2     = (const float*)d_in[5];
    const float* w_sum  = (const float*)d_in[6];
    const float* wq     = (const float*)d_in[7];
    const float* wk     = (const float*)d_in[8];
    const float* wv     = (const float*)d_in[9];
    float* out = (float*)d_out;
    (void)in_sizes; (void)n_in;

    float *ph, *pq, *pst, *psum, *ppool, *pk, *pkT, *pv, *pattn;
    cudaGetSymbolAddress((void**)&ph,    g_h);
    cudaGetSymbolAddress((void**)&pq,    g_q);
    cudaGetSymbolAddress((void**)&pst,   g_st);
    cudaGetSymbolAddress((void**)&psum,  g_sum);
    cudaGetSymbolAddress((void**)&ppool, g_pool);
    cudaGetSymbolAddress((void**)&pk,    g_k);
    cudaGetSymbolAddress((void**)&pkT,   g_kT);
    cudaGetSymbolAddress((void**)&pv,    g_v);
    cudaGetSymbolAddress((void**)&pattn, g_attn);

    // 1. h = tokens @ w1   [16384,1024]@[1024,256]
    sgemm128_kernel<<<dim3(NH / 128, NBT / 128, 1), 256>>>(tokens, w1, ph, NBT, NH, ND, 0, 0, 0);
    // 2. q = tokens @ wq
    sgemm128_kernel<<<dim3(NS / 128, NBT / 128, 1), 256>>>(tokens, wq, pq, NBT, NS, ND, 0, 0, 0);
    // 3. scores (fp32 fast pass)
    score_kernel<<<NBT / 8, 256>>>(w2);
    // 4. provisional sort
    sort_kernel<<<NB, 1024>>>();
    // 5. flag at-risk tokens and recompute them exactly (fp64)
    reset_flags_kernel<<<NBT / 256, 256>>>();
    flag_ab_kernel<<<NBT / 256, 256>>>();
    flag_c_kernel<<<dim3(NT / 256, NB), 256>>>(pri);
    compact_kernel<<<NBT / 256, 256>>>();
    recompute_kernel<<<512, 256>>>(tokens, w1, w2);
    // 6. final sort with corrected scores
    sort_kernel<<<NB, 1024>>>();
    // 7. gather top-512 tokens
    gather_kernel<<<dim3(NP, NB), 256>>>(tokens);
    // 8. summaries = sorted_tokens @ w_sum   [4096,1024]@[1024,256]
    sgemm128_kernel<<<dim3(NS / 128, NB * NP / 128, 1), 256>>>(pst, w_sum, psum, NB * NP, NS, ND, 0, 0, 0);
    // 9. sequential pool update
    update_kernel<<<NB, 256>>>(pool, pri, counts);
    // 10. k = pool @ wk   [4096,256]@[256,256]
    sgemm128_kernel<<<dim3(NS / 128, NB * NP / 128, 1), 256>>>(ppool, wk, pk, NB * NP, NS, NS, 0, 0, 0);
    // 11. transpose k -> kT
    transpose_kernel<<<dim3(NP / 32, NS / 32, NB), dim3(32, 8)>>>();
    // 12. v = pool @ wv   [4096,256]@[256,1024]
    sgemm128_kernel<<<dim3(ND / 128, NB * NP / 128, 1), 256>>>(ppool, wv, pv, NB * NP, ND, NS, 0, 0, 0);
    // 13. attn = q @ kT  batched [2048,256]@[256,512]
    sgemm128_kernel<<<dim3(NP / 128, NT / 128, NB), 256>>>(pq, pkT, pattn, NT, NP, NS,
        (long long)NT * NS, (long long)NS * NP, (long long)NT * NP);
    // 14. masked softmax
    softmax_kernel<<<NBT / 8, 256>>>();
    // 15. retrieved = attn @ v  batched [2048,512]@[512,1024] -> d_out
    sgemm128_kernel<<<dim3(ND / 128, NT / 128, NB), 256>>>(pattn, pv, out, NT, ND, NP,
        (long long)NT * NP, (long long)NP * ND, (long long)NT * ND);
    // 16. export pool / priorities / counts
    constexpr int RET = NBT * ND;
    constexpr int REST = NB * NP * NS + NB * NP + NB;
    if (out_size >= RET + REST)
        export_kernel<<<(REST + 255) / 256, 256>>>(out + (long long)RET);
}